// round 4
// baseline (speedup 1.0000x reference)
#include <cuda_runtime.h>

// Problem constants
#define BV   8
#define CV   19
#define HWv  (512 * 1024)              // 524288 = 2^19
#define NPIX (BV * HWv)                // 4194304
#define THREADS 256
#define PIX_PER_THREAD 8
#define NBLOCKS (NPIX / (THREADS * PIX_PER_THREAD))   // 2048

__device__ float g_partials[NBLOCKS];

__global__ __launch_bounds__(THREADS)
void ce_main_kernel(const float* __restrict__ logits,
                    const int*   __restrict__ labels) {
    const int tid  = blockIdx.x * THREADS + threadIdx.x;
    const int base = tid * PIX_PER_THREAD;          // first pixel of this thread
    const int b    = base >> 19;                    // image index (HW = 2^19)
    const int pix  = base & (HWv - 1);              // pixel within image

    const float4* lp =
        reinterpret_cast<const float4*>(logits + (size_t)b * CV * HWv + pix);
    const int4 lab0 = __ldcs(reinterpret_cast<const int4*>(labels + base));
    const int4 lab1 = __ldcs(reinterpret_cast<const int4*>(labels + base) + 1);

    float4 s0 = make_float4(0.f, 0.f, 0.f, 0.f);
    float4 s1 = make_float4(0.f, 0.f, 0.f, 0.f);
    float4 x0 = make_float4(0.f, 0.f, 0.f, 0.f);
    float4 x1 = make_float4(0.f, 0.f, 0.f, 0.f);

    #pragma unroll
    for (int c = 0; c < CV; ++c) {
        const float4 v0 = __ldcs(lp + c * (HWv / 4));       // pixels base..base+3
        const float4 v1 = __ldcs(lp + c * (HWv / 4) + 1);   // pixels base+4..base+7
        s0.x += __expf(v0.x);  s0.y += __expf(v0.y);
        s0.z += __expf(v0.z);  s0.w += __expf(v0.w);
        s1.x += __expf(v1.x);  s1.y += __expf(v1.y);
        s1.z += __expf(v1.z);  s1.w += __expf(v1.w);
        if (c == lab0.x) x0.x = v0.x;
        if (c == lab0.y) x0.y = v0.y;
        if (c == lab0.z) x0.z = v0.z;
        if (c == lab0.w) x0.w = v0.w;
        if (c == lab1.x) x1.x = v1.x;
        if (c == lab1.y) x1.y = v1.y;
        if (c == lab1.z) x1.z = v1.z;
        if (c == lab1.w) x1.w = v1.w;
    }

    // nll = log(sum exp) - x_label ; zero at ignored pixels (label < 0)
    float loss = 0.f;
    loss += (lab0.x >= 0) ? (__logf(s0.x) - x0.x) : 0.f;
    loss += (lab0.y >= 0) ? (__logf(s0.y) - x0.y) : 0.f;
    loss += (lab0.z >= 0) ? (__logf(s0.z) - x0.z) : 0.f;
    loss += (lab0.w >= 0) ? (__logf(s0.w) - x0.w) : 0.f;
    loss += (lab1.x >= 0) ? (__logf(s1.x) - x1.x) : 0.f;
    loss += (lab1.y >= 0) ? (__logf(s1.y) - x1.y) : 0.f;
    loss += (lab1.z >= 0) ? (__logf(s1.z) - x1.z) : 0.f;
    loss += (lab1.w >= 0) ? (__logf(s1.w) - x1.w) : 0.f;

    // warp reduce
    #pragma unroll
    for (int o = 16; o > 0; o >>= 1)
        loss += __shfl_down_sync(0xFFFFFFFFu, loss, o);

    __shared__ float ws[THREADS / 32];
    if ((threadIdx.x & 31) == 0) ws[threadIdx.x >> 5] = loss;
    __syncthreads();

    if (threadIdx.x < (THREADS / 32)) {
        float v = ws[threadIdx.x];
        #pragma unroll
        for (int o = (THREADS / 64); o > 0; o >>= 1)
            v += __shfl_down_sync(0xFFu, v, o);
        if (threadIdx.x == 0) g_partials[blockIdx.x] = v;
    }
}

// Secondary kernel: launched with PDL so its launch latency overlaps the
// primary. Waits on the grid dependency before reading g_partials.
__global__ __launch_bounds__(256)
void ce_reduce_kernel(float* __restrict__ out) {
    cudaGridDependencySynchronize();

    // 2048 floats = 512 float4; 256 threads x 2 float4 each
    const float4* p = reinterpret_cast<const float4*>(g_partials);
    float s = 0.f;
    #pragma unroll
    for (int i = 0; i < 2; ++i) {
        float4 v = p[threadIdx.x + i * 256];
        s += (v.x + v.y) + (v.z + v.w);
    }

    #pragma unroll
    for (int o = 16; o > 0; o >>= 1)
        s += __shfl_down_sync(0xFFFFFFFFu, s, o);

    __shared__ float ws[8];
    if ((threadIdx.x & 31) == 0) ws[threadIdx.x >> 5] = s;
    __syncthreads();

    if (threadIdx.x == 0) {
        float v = 0.f;
        #pragma unroll
        for (int w = 0; w < 8; ++w) v += ws[w];
        out[0] = v * (1.0f / (float)NPIX);
    }
}

extern "C" void kernel_launch(void* const* d_in, const int* in_sizes, int n_in,
                              void* d_out, int out_size) {
    const float* logits = (const float*)d_in[0];
    const int*   labels = (const int*)d_in[1];
    // d_in[2] (smooth_labels) is dead in the reference forward — never read.
    float* out = (float*)d_out;

    ce_main_kernel<<<NBLOCKS, THREADS>>>(logits, labels);

    // PDL launch of the reduce: overlap its launch with the primary's tail.
    cudaLaunchConfig_t cfg = {};
    cfg.gridDim  = dim3(1, 1, 1);
    cfg.blockDim = dim3(256, 1, 1);
    cfg.dynamicSmemBytes = 0;
    cfg.stream = 0;
    cudaLaunchAttribute attr[1];
    attr[0].id = cudaLaunchAttributeProgrammaticStreamSerialization;
    attr[0].val.programmaticStreamSerializationAllowed = 1;
    cfg.attrs = attr;
    cfg.numAttrs = 1;
    cudaLaunchKernelEx(&cfg, ce_reduce_kernel, out);
}

// round 6
// speedup vs baseline: 1.0426x; 1.0426x over previous
#include <cuda_runtime.h>

// Problem constants
#define BV   8
#define CV   19
#define HWv  (512 * 1024)              // 524288 = 2^19
#define NPIX (BV * HWv)                // 4194304
#define THREADS 256
#define PIX_PER_THREAD 4
#define NBLOCKS (NPIX / (THREADS * PIX_PER_THREAD))   // 4096

__device__ float g_partials[NBLOCKS];

__global__ __launch_bounds__(THREADS)
void ce_main_kernel(const float* __restrict__ logits,
                    const int*   __restrict__ labels) {
    const int tid  = blockIdx.x * THREADS + threadIdx.x;
    const int base = tid * PIX_PER_THREAD;          // first pixel of this thread
    const int b    = base >> 19;                    // image index (HW = 2^19)
    const int pix  = base & (HWv - 1);              // pixel within image

    const float4* lp =
        reinterpret_cast<const float4*>(logits + (size_t)b * CV * HWv + pix);
    const int4 lab = __ldcs(reinterpret_cast<const int4*>(labels + base));

    float4 s  = make_float4(0.f, 0.f, 0.f, 0.f);
    float4 xl = make_float4(0.f, 0.f, 0.f, 0.f);

    #pragma unroll
    for (int c = 0; c < CV; ++c) {
        const float4 v = __ldcs(lp + c * (HWv / 4));   // streaming: evict-first
        s.x += __expf(v.x);
        s.y += __expf(v.y);
        s.z += __expf(v.z);
        s.w += __expf(v.w);
        if (c == lab.x) xl.x = v.x;
        if (c == lab.y) xl.y = v.y;
        if (c == lab.z) xl.z = v.z;
        if (c == lab.w) xl.w = v.w;
    }

    // nll = log(sum exp) - x_label ; zero at ignored pixels (label < 0)
    float loss = 0.f;
    loss += (lab.x >= 0) ? (__logf(s.x) - xl.x) : 0.f;
    loss += (lab.y >= 0) ? (__logf(s.y) - xl.y) : 0.f;
    loss += (lab.z >= 0) ? (__logf(s.z) - xl.z) : 0.f;
    loss += (lab.w >= 0) ? (__logf(s.w) - xl.w) : 0.f;

    // warp reduce
    #pragma unroll
    for (int o = 16; o > 0; o >>= 1)
        loss += __shfl_down_sync(0xFFFFFFFFu, loss, o);

    __shared__ float ws[THREADS / 32];
    if ((threadIdx.x & 31) == 0) ws[threadIdx.x >> 5] = loss;
    __syncthreads();

    if (threadIdx.x < (THREADS / 32)) {
        float v = ws[threadIdx.x];
        #pragma unroll
        for (int o = (THREADS / 64); o > 0; o >>= 1)
            v += __shfl_down_sync(0xFFu, v, o);
        if (threadIdx.x == 0) g_partials[blockIdx.x] = v;
    }

    // Release the PDL dependency as soon as this CTA's partial is written,
    // so the reduce kernel unblocks at last-data-ready instead of after the
    // full grid teardown.
    __syncthreads();
    cudaTriggerProgrammaticLaunchCompletion();
}

// Secondary kernel: launched with PDL so its launch latency overlaps the
// primary. Waits on the grid dependency before reading g_partials.
__global__ __launch_bounds__(256)
void ce_reduce_kernel(float* __restrict__ out) {
    cudaGridDependencySynchronize();

    // 4096 floats = 1024 float4; 256 threads x 4 float4 each, MLP=4
    const float4* p = reinterpret_cast<const float4*>(g_partials);
    float s = 0.f;
    #pragma unroll
    for (int i = 0; i < 4; ++i) {
        float4 v = p[threadIdx.x + i * 256];
        s += (v.x + v.y) + (v.z + v.w);
    }

    #pragma unroll
    for (int o = 16; o > 0; o >>= 1)
        s += __shfl_down_sync(0xFFFFFFFFu, s, o);

    __shared__ float ws[8];
    if ((threadIdx.x & 31) == 0) ws[threadIdx.x >> 5] = s;
    __syncthreads();

    if (threadIdx.x == 0) {
        float v = 0.f;
        #pragma unroll
        for (int w = 0; w < 8; ++w) v += ws[w];
        out[0] = v * (1.0f / (float)NPIX);
    }
}

extern "C" void kernel_launch(void* const* d_in, const int* in_sizes, int n_in,
                              void* d_out, int out_size) {
    const float* logits = (const float*)d_in[0];
    const int*   labels = (const int*)d_in[1];
    // d_in[2] (smooth_labels) is dead in the reference forward — never read.
    float* out = (float*)d_out;

    ce_main_kernel<<<NBLOCKS, THREADS>>>(logits, labels);

    // PDL launch of the reduce: overlap its launch with the primary's tail.
    cudaLaunchConfig_t cfg = {};
    cfg.gridDim  = dim3(1, 1, 1);
    cfg.blockDim = dim3(256, 1, 1);
    cfg.dynamicSmemBytes = 0;
    cfg.stream = 0;
    cudaLaunchAttribute attr[1];
    attr[0].id = cudaLaunchAttributeProgrammaticStreamSerialization;
    attr[0].val.programmaticStreamSerializationAllowed = 1;
    cfg.attrs = attr;
    cfg.numAttrs = 1;
    cudaLaunchKernelEx(&cfg, ce_reduce_kernel, out);
}